// round 2
// baseline (speedup 1.0000x reference)
#include <cuda_runtime.h>
#include <cuda_bf16.h>
#include <cstdint>

// Problem constants (shapes fixed by the reference)
#define C_DIM 64
#define K_DIM 32
#define B_DIM 16
#define EPSF  1e-9f

// Output layout (tuple flattened in return order):
// out[B,K,C]=32768 | s[N,K]=N*32 | entropy | diversity | spatial | pruning |
// sparsity | separation | mu[B,K,2]=1024
#define OFF_OUT   0
#define OUT_ELEMS (B_DIM * K_DIM * C_DIM)              // 32768
#define OFF_S     OUT_ELEMS

// ---------------- device scratch (no allocations allowed) ----------------
__device__ float g_ent;
__device__ float g_ss[B_DIM * K_DIM];
__device__ float g_spp[B_DIM * K_DIM * 2];
__device__ float g_spq[K_DIM];
__device__ int   g_start[B_DIM + 1];

// ---------------- packed f32x2 helpers ----------------
__device__ __forceinline__ unsigned long long pack2(float lo, float hi) {
    unsigned long long r;
    asm("mov.b64 %0, {%1, %2};" : "=l"(r) : "f"(lo), "f"(hi));
    return r;
}
__device__ __forceinline__ void unpack2(unsigned long long v, float& lo, float& hi) {
    asm("mov.b64 {%0, %1}, %2;" : "=f"(lo), "=f"(hi) : "l"(v));
}
__device__ __forceinline__ unsigned long long fma2(unsigned long long a,
                                                   unsigned long long b,
                                                   unsigned long long c) {
    unsigned long long d;
    asm("fma.rn.f32x2 %0, %1, %2, %3;" : "=l"(d) : "l"(a), "l"(b), "l"(c));
    return d;
}

// ---------------- kernel 0: zero scratch + out region ----------------
__global__ void hp_zero_kernel(float* __restrict__ out, int N) {
    int i = blockIdx.x * blockDim.x + threadIdx.x;
    int stride = gridDim.x * blockDim.x;
    for (int j = i; j < OUT_ELEMS; j += stride) out[j] = 0.0f;
    for (int j = i; j < B_DIM * K_DIM; j += stride) {
        g_ss[j] = 0.0f;
        g_spp[2 * j] = 0.0f;
        g_spp[2 * j + 1] = 0.0f;
    }
    if (i < K_DIM) g_spq[i] = 0.0f;
    if (i == 0) g_ent = 0.0f;
    if (i <= B_DIM) g_start[i] = N;
}

// ---------------- kernel 1: graph boundaries (batch is sorted) ----------------
__global__ void hp_bound_kernel(const int* __restrict__ batch, int N) {
    int n = blockIdx.x * blockDim.x + threadIdx.x;
    int stride = gridDim.x * blockDim.x;
    for (; n < N; n += stride) {
        if (n == 0 || batch[n] != batch[n - 1]) {
            atomicMin(&g_start[batch[n]], n);
        }
    }
}
__global__ void hp_fix_kernel(int N) {
    g_start[B_DIM] = N;
    for (int b = B_DIM - 1; b >= 0; b--)
        if (g_start[b] > g_start[b + 1]) g_start[b] = g_start[b + 1];
}

// ---------------- assign epilogue: gumbel softmax + entropy for one node ----
__device__ __forceinline__ float hp_epilogue(const unsigned long long* l2,
                                             const float* __restrict__ u, int n,
                                             float scal, const float* msk,
                                             float* __restrict__ s_out) {
    float l[K_DIM];
    #pragma unroll
    for (int k = 0; k < K_DIM / 2; k++) unpack2(l2[k], l[2 * k], l[2 * k + 1]);

    const float4* uv = (const float4*)(u + (size_t)n * K_DIM);
    float z[K_DIM];
    float m = -3.4e38f;
    #pragma unroll
    for (int kc = 0; kc < 8; kc++) {
        float4 uq = uv[kc];
        float ue[4] = {uq.x, uq.y, uq.z, uq.w};
        #pragma unroll
        for (int q = 0; q < 4; q++) {
            int k = kc * 4 + q;
            float lg = l[k] * scal;
            lg = (msk[k] == 0.0f) ? -1e9f : lg;
            float g = -__logf(-__logf(ue[q] + EPSF) + EPSF);
            float zz = lg + g;   // TAU = 1
            z[k] = zz;
            m = fmaxf(m, zz);
        }
    }
    float ssum = 0.0f;
    #pragma unroll
    for (int k = 0; k < K_DIM; k++) {
        float e = __expf(z[k] - m);
        z[k] = e;
        ssum += e;
    }
    float inv = 1.0f / ssum;

    float ent = 0.0f;
    float4* so = (float4*)(s_out + (size_t)n * K_DIM);
    #pragma unroll
    for (int kc = 0; kc < 8; kc++) {
        float s0 = z[kc * 4 + 0] * inv;
        float s1 = z[kc * 4 + 1] * inv;
        float s2 = z[kc * 4 + 2] * inv;
        float s3 = z[kc * 4 + 3] * inv;
        ent += s0 * __logf(s0 + EPSF) + s1 * __logf(s1 + EPSF)
             + s2 * __logf(s2 + EPSF) + s3 * __logf(s3 + EPSF);
        so[kc] = make_float4(s0, s1, s2, s3);
    }
    return ent;
}

// ---------------- kernel A: MLP + gumbel softmax (2 nodes/thread) ----------
#define AB_THREADS 128
__global__ __launch_bounds__(AB_THREADS, 4)
void hp_assign_kernel(const float* __restrict__ x,
                      const float* __restrict__ u,
                      const float* __restrict__ W1,
                      const float* __restrict__ b1,
                      const float* __restrict__ W2,
                      const float* __restrict__ b2,
                      const float* __restrict__ scaling,
                      const float* __restrict__ amask,
                      float* __restrict__ s_out,
                      int N) {
    __shared__ __align__(16) float W1s[C_DIM * C_DIM];   // [j][i]
    __shared__ __align__(16) float W2s[C_DIM * K_DIM];   // [i][k]
    __shared__ __align__(16) float b1s[C_DIM];
    __shared__ __align__(16) float b2s[K_DIM];
    __shared__ float msk[K_DIM];
    __shared__ float scal;

    int t = threadIdx.x;
    for (int i = t; i < C_DIM * C_DIM; i += AB_THREADS) W1s[i] = W1[i];
    for (int i = t; i < C_DIM * K_DIM; i += AB_THREADS) W2s[i] = W2[i];
    if (t < C_DIM) b1s[t] = b1[t];
    if (t < K_DIM) { b2s[t] = b2[t]; msk[t] = amask[t]; }
    if (t == 0) scal = scaling[0];
    __syncthreads();

    // block covers 256 nodes; thread t handles n0 = base+t and n1 = base+t+128
    int base = blockIdx.x * 256;
    int n0 = base + t;
    int n1 = n0 + AB_THREADS;
    bool v0 = n0 < N, v1 = n1 < N;

    unsigned long long lA[K_DIM / 2], lB[K_DIM / 2];
    #pragma unroll
    for (int k = 0; k < K_DIM / 2; k++) {
        unsigned long long b = pack2(b2s[2 * k], b2s[2 * k + 1]);
        lA[k] = b;
        lB[k] = b;
    }

    const float4* xa = (const float4*)(x + (size_t)n0 * C_DIM);
    const float4* xb = (const float4*)(x + (size_t)n1 * C_DIM);
    const ulonglong2* W1q = (const ulonglong2*)W1s;   // 16 u128 per row of 64
    const ulonglong2* W2q = (const ulonglong2*)W2s;   // 8 u128 per row of 32

    // 4 passes over hidden, 16 hidden units per pass
    #pragma unroll
    for (int p = 0; p < 4; p++) {
        unsigned long long hA[8], hB[8];
        #pragma unroll
        for (int m = 0; m < 8; m++) {
            unsigned long long b = pack2(b1s[p * 16 + 2 * m], b1s[p * 16 + 2 * m + 1]);
            hA[m] = b;
            hB[m] = b;
        }

        #pragma unroll
        for (int jc = 0; jc < 16; jc++) {
            float4 qa = v0 ? xa[jc] : make_float4(0.f, 0.f, 0.f, 0.f);
            float4 qb = v1 ? xb[jc] : make_float4(0.f, 0.f, 0.f, 0.f);
            float ea[4] = {qa.x, qa.y, qa.z, qa.w};
            float eb[4] = {qb.x, qb.y, qb.z, qb.w};
            #pragma unroll
            for (int q = 0; q < 4; q++) {
                int j = jc * 4 + q;
                unsigned long long a2 = pack2(ea[q], ea[q]);
                unsigned long long c2 = pack2(eb[q], eb[q]);
                const ulonglong2* row = W1q + j * 16 + p * 4;
                #pragma unroll
                for (int i4 = 0; i4 < 4; i4++) {
                    ulonglong2 w = row[i4];
                    hA[2 * i4]     = fma2(a2, w.x, hA[2 * i4]);
                    hA[2 * i4 + 1] = fma2(a2, w.y, hA[2 * i4 + 1]);
                    hB[2 * i4]     = fma2(c2, w.x, hB[2 * i4]);
                    hB[2 * i4 + 1] = fma2(c2, w.y, hB[2 * i4 + 1]);
                }
            }
        }

        // GEMM2 partial: relu(h_chunk) @ W2 rows [p*16, p*16+16)
        #pragma unroll
        for (int iu = 0; iu < 8; iu++) {
            float a0, a1, c0, c1;
            unpack2(hA[iu], a0, a1);
            unpack2(hB[iu], c0, c1);
            a0 = fmaxf(a0, 0.f); a1 = fmaxf(a1, 0.f);
            c0 = fmaxf(c0, 0.f); c1 = fmaxf(c1, 0.f);
            unsigned long long ha0 = pack2(a0, a0), ha1 = pack2(a1, a1);
            unsigned long long hb0 = pack2(c0, c0), hb1 = pack2(c1, c1);
            int i0 = p * 16 + iu * 2;
            const ulonglong2* r0 = W2q + i0 * 8;
            const ulonglong2* r1 = r0 + 8;
            #pragma unroll
            for (int k2 = 0; k2 < 8; k2++) {
                ulonglong2 w = r0[k2];
                lA[2 * k2]     = fma2(ha0, w.x, lA[2 * k2]);
                lA[2 * k2 + 1] = fma2(ha0, w.y, lA[2 * k2 + 1]);
                lB[2 * k2]     = fma2(hb0, w.x, lB[2 * k2]);
                lB[2 * k2 + 1] = fma2(hb0, w.y, lB[2 * k2 + 1]);
            }
            #pragma unroll
            for (int k2 = 0; k2 < 8; k2++) {
                ulonglong2 w = r1[k2];
                lA[2 * k2]     = fma2(ha1, w.x, lA[2 * k2]);
                lA[2 * k2 + 1] = fma2(ha1, w.y, lA[2 * k2 + 1]);
                lB[2 * k2]     = fma2(hb1, w.x, lB[2 * k2]);
                lB[2 * k2 + 1] = fma2(hb1, w.y, lB[2 * k2 + 1]);
            }
        }
    }

    float ent_local = 0.0f;
    if (v0) ent_local += hp_epilogue(lA, u, n0, scal, msk, s_out);
    if (v1) ent_local += hp_epilogue(lB, u, n1, scal, msk, s_out);

    // block-reduce entropy, one atomic per block
    #pragma unroll
    for (int o = 16; o; o >>= 1) ent_local += __shfl_xor_sync(0xffffffffu, ent_local, o);
    __shared__ float wsum[4];
    if ((t & 31) == 0) wsum[t >> 5] = ent_local;
    __syncthreads();
    if (t == 0) {
        atomicAdd(&g_ent, wsum[0] + wsum[1] + wsum[2] + wsum[3]);
    }
}

// ---------------- kernel B: pooled features + centroid sums ----------------
#define PSPLITS 64
__global__ __launch_bounds__(256)
void hp_pool_kernel(const float* __restrict__ x,
                    const float* __restrict__ pos,
                    const float* __restrict__ s,
                    float* __restrict__ out) {
    int b = blockIdx.y;
    int n0 = g_start[b], n1 = g_start[b + 1];
    int cnt = n1 - n0;
    int chunk = (cnt + PSPLITS - 1) / PSPLITS;
    int s0 = n0 + blockIdx.x * chunk;
    int s1 = min(s0 + chunk, n1);
    if (s0 >= s1) return;

    __shared__ __align__(16) float ssh[64][33];
    __shared__ __align__(16) float xsh[64][68];
    __shared__ float psh[64][2];

    int t = threadIdx.x;
    int k = t & 31;
    int grp = t >> 5;   // warp id 0..7, c-slice = grp*8..grp*8+8

    unsigned long long acc2[4];
    #pragma unroll
    for (int j = 0; j < 4; j++) acc2[j] = 0ull;
    float ass = 0.0f, apx = 0.0f, apy = 0.0f, aq = 0.0f;

    for (int tile = s0; tile < s1; tile += 64) {
        // stage s tile [64 nodes][32 k], float4 loads, scalar conflict-free stores
        for (int idx = t; idx < 64 * 8; idx += 256) {
            int node = idx >> 3, kg = idx & 7;
            int gn = tile + node;
            float4 v = (gn < s1) ? ((const float4*)(s + (size_t)gn * K_DIM))[kg]
                                 : make_float4(0.f, 0.f, 0.f, 0.f);
            ssh[node][kg * 4 + 0] = v.x;
            ssh[node][kg * 4 + 1] = v.y;
            ssh[node][kg * 4 + 2] = v.z;
            ssh[node][kg * 4 + 3] = v.w;
        }
        // stage x tile [64][64], vector stores
        for (int idx = t; idx < 64 * 16; idx += 256) {
            int node = idx >> 4, cg = idx & 15;
            int gn = tile + node;
            float4 v = (gn < s1) ? ((const float4*)(x + (size_t)gn * C_DIM))[cg]
                                 : make_float4(0.f, 0.f, 0.f, 0.f);
            *(float4*)(&xsh[node][cg * 4]) = v;
        }
        // stage pos tile
        if (t < 128) {
            int node = t >> 1, d = t & 1;
            int gn = tile + node;
            psh[node][d] = (gn < s1) ? pos[(size_t)gn * 2 + d] : 0.0f;
        }
        __syncthreads();

        #pragma unroll 8
        for (int nn = 0; nn < 64; nn++) {
            float sv = ssh[nn][k];
            unsigned long long sv2 = pack2(sv, sv);
            const ulonglong2* xr = (const ulonglong2*)(&xsh[nn][grp * 8]);
            ulonglong2 x0 = xr[0];
            acc2[0] = fma2(sv2, x0.x, acc2[0]);
            acc2[1] = fma2(sv2, x0.y, acc2[1]);
            ulonglong2 x1 = xr[1];
            acc2[2] = fma2(sv2, x1.x, acc2[2]);
            acc2[3] = fma2(sv2, x1.y, acc2[3]);
            if (grp == 0) {
                float px = psh[nn][0], py = psh[nn][1];
                ass += sv;
                apx += sv * px;
                apy += sv * py;
                aq  += sv * (px * px + py * py);
            }
        }
        __syncthreads();
    }

    float accf[8];
    #pragma unroll
    for (int j = 0; j < 4; j++) unpack2(acc2[j], accf[2 * j], accf[2 * j + 1]);
    #pragma unroll
    for (int j = 0; j < 8; j++)
        atomicAdd(&out[OFF_OUT + ((size_t)b * K_DIM + k) * C_DIM + grp * 8 + j], accf[j]);
    if (grp == 0) {
        int bk = b * K_DIM + k;
        atomicAdd(&g_ss[bk], ass);
        atomicAdd(&g_spp[2 * bk + 0], apx);
        atomicAdd(&g_spp[2 * bk + 1], apy);
        atomicAdd(&g_spq[k], aq);
    }
}

// ---------------- kernel C: finalize scalars, mu, separation ----------------
__global__ __launch_bounds__(512)
void hp_final_kernel(const float* __restrict__ amask, float* __restrict__ out, int N) {
    __shared__ float mush[B_DIM * K_DIM][2];
    __shared__ float red[16];

    const size_t off_scalars = (size_t)OFF_S + (size_t)N * K_DIM;
    const size_t OFF_ENT  = off_scalars + 0;
    const size_t OFF_DIV  = off_scalars + 1;
    const size_t OFF_SPAT = off_scalars + 2;
    const size_t OFF_PRUN = off_scalars + 3;
    const size_t OFF_SPAR = off_scalars + 4;
    const size_t OFF_SEP  = off_scalars + 5;
    const size_t OFF_MU   = off_scalars + 6;

    int t = threadIdx.x;        // 512 = B*K
    int bk = t;
    float ssv = g_ss[bk];
    float denom = ssv + EPSF;
    float mux = g_spp[2 * bk] / denom;
    float muy = g_spp[2 * bk + 1] / denom;
    mush[bk][0] = mux;
    mush[bk][1] = muy;
    out[OFF_MU + 2 * bk] = mux;
    out[OFF_MU + 2 * bk + 1] = muy;
    __syncthreads();

    int b = bk >> 5, k1 = bk & 31;
    float sep = 0.0f;
    #pragma unroll
    for (int k2 = 0; k2 < K_DIM; k2++) {
        if (k2 == k1) continue;
        float dx = mux - mush[b * K_DIM + k2][0];
        float dy = muy - mush[b * K_DIM + k2][1];
        sep += 1.0f / (dx * dx + dy * dy + 1.0f);
    }
    #pragma unroll
    for (int o = 16; o; o >>= 1) sep += __shfl_xor_sync(0xffffffffu, sep, o);
    if ((t & 31) == 0) red[t >> 5] = sep;
    __syncthreads();

    if (t == 0) {
        float tot = 0.0f;
        for (int i = 0; i < 16; i++) tot += red[i];
        out[OFF_SEP] = tot / ((float)(K_DIM * (K_DIM - 1)) + EPSF);

        float div = 0.0f, spat = 0.0f, prun = 0.0f, spars = 0.0f;
        for (int k = 0; k < K_DIM; k++) {
            float ss = 0.0f, sx = 0.0f, sy = 0.0f;
            for (int bb = 0; bb < B_DIM; bb++) {
                int idx = bb * K_DIM + k;
                ss += g_ss[idx];
                sx += g_spp[2 * idx];
                sy += g_spp[2 * idx + 1];
            }
            float avg = ss / (float)N;
            div += avg * __logf(avg + EPSF);
            float sse = ss + EPSF;
            float mgx = sx / sse, mgy = sy / sse;
            float var = g_spq[k] / sse
                        - 2.0f * (mgx * (sx / sse) + mgy * (sy / sse))
                        + (mgx * mgx + mgy * mgy);
            spat += var;
            float mk = amask[k];
            prun += fabsf(avg * (1.0f - mk));
            spars += mk;
        }
        out[OFF_ENT]  = -g_ent / (float)N;
        out[OFF_DIV]  = div;
        out[OFF_SPAT] = spat / (float)K_DIM;
        out[OFF_PRUN] = prun / (float)K_DIM;
        out[OFF_SPAR] = spars / (float)K_DIM;
    }
}

// ---------------- launcher ----------------
extern "C" void kernel_launch(void* const* d_in, const int* in_sizes, int n_in,
                              void* d_out, int out_size) {
    (void)n_in; (void)out_size;
    const float* x       = (const float*)d_in[0];
    const int*   batch   = (const int*)d_in[1];
    const float* pos     = (const float*)d_in[2];
    const float* u       = (const float*)d_in[3];
    const float* W1      = (const float*)d_in[4];
    const float* b1      = (const float*)d_in[5];
    const float* W2      = (const float*)d_in[6];
    const float* b2      = (const float*)d_in[7];
    const float* scaling = (const float*)d_in[8];
    const float* amask   = (const float*)d_in[9];
    float* out = (float*)d_out;

    int N = in_sizes[0] / C_DIM;

    hp_zero_kernel<<<64, 256>>>(out, N);
    hp_bound_kernel<<<256, 256>>>(batch, N);
    hp_fix_kernel<<<1, 1>>>(N);
    hp_assign_kernel<<<(N + 255) / 256, AB_THREADS>>>(x, u, W1, b1, W2, b2, scaling,
                                                      amask, out + OFF_S, N);
    hp_pool_kernel<<<dim3(PSPLITS, B_DIM), 256>>>(x, pos, out + OFF_S, out);
    hp_final_kernel<<<1, 512>>>(amask, out, N);
}

// round 3
// speedup vs baseline: 1.0029x; 1.0029x over previous
#include <cuda_runtime.h>
#include <cuda_bf16.h>
#include <cstdint>

// Problem constants (shapes fixed by the reference)
#define C_DIM 64
#define K_DIM 32
#define B_DIM 16
#define EPSF  1e-9f

// Output layout (tuple flattened in return order):
// out[B,K,C]=32768 | s[N,K]=N*32 | entropy | diversity | spatial | pruning |
// sparsity | separation | mu[B,K,2]=1024
#define OFF_OUT   0
#define OUT_ELEMS (B_DIM * K_DIM * C_DIM)              // 32768
#define OFF_S     OUT_ELEMS

// ---------------- device scratch (no allocations allowed) ----------------
__device__ float g_ent;
__device__ float g_ss[B_DIM * K_DIM];
__device__ float g_spp[B_DIM * K_DIM * 2];
__device__ float g_spq[K_DIM];
__device__ int   g_start[B_DIM + 1];

// ---------------- packed f32x2 helpers ----------------
__device__ __forceinline__ unsigned long long pack2(float lo, float hi) {
    unsigned long long r;
    asm("mov.b64 %0, {%1, %2};" : "=l"(r) : "f"(lo), "f"(hi));
    return r;
}
__device__ __forceinline__ void unpack2(unsigned long long v, float& lo, float& hi) {
    asm("mov.b64 {%0, %1}, %2;" : "=f"(lo), "=f"(hi) : "l"(v));
}
__device__ __forceinline__ unsigned long long fma2(unsigned long long a,
                                                   unsigned long long b,
                                                   unsigned long long c) {
    unsigned long long d;
    asm("fma.rn.f32x2 %0, %1, %2, %3;" : "=l"(d) : "l"(a), "l"(b), "l"(c));
    return d;
}

// ---------------- kernel 0: zero scratch + out region ----------------
__global__ void hp_zero_kernel(float* __restrict__ out, int N) {
    int i = blockIdx.x * blockDim.x + threadIdx.x;
    int stride = gridDim.x * blockDim.x;
    for (int j = i; j < OUT_ELEMS; j += stride) out[j] = 0.0f;
    for (int j = i; j < B_DIM * K_DIM; j += stride) {
        g_ss[j] = 0.0f;
        g_spp[2 * j] = 0.0f;
        g_spp[2 * j + 1] = 0.0f;
    }
    if (i < K_DIM) g_spq[i] = 0.0f;
    if (i == 0) g_ent = 0.0f;
    if (i <= B_DIM) g_start[i] = N;
}

// ---------------- kernel 1: graph boundaries (batch is sorted) ----------------
__global__ void hp_bound_kernel(const int* __restrict__ batch, int N) {
    int n = blockIdx.x * blockDim.x + threadIdx.x;
    int stride = gridDim.x * blockDim.x;
    for (; n < N; n += stride) {
        if (n == 0 || batch[n] != batch[n - 1]) {
            atomicMin(&g_start[batch[n]], n);
        }
    }
}
__global__ void hp_fix_kernel(int N) {
    g_start[B_DIM] = N;
    for (int b = B_DIM - 1; b >= 0; b--)
        if (g_start[b] > g_start[b + 1]) g_start[b] = g_start[b + 1];
}

// ---------------- assign epilogue: gumbel softmax + entropy for one node ----
__device__ __forceinline__ float hp_epilogue(const unsigned long long* l2,
                                             const float* __restrict__ u, int n,
                                             float scal, const float* msk,
                                             float* __restrict__ s_out) {
    float l[K_DIM];
    #pragma unroll
    for (int k = 0; k < K_DIM / 2; k++) unpack2(l2[k], l[2 * k], l[2 * k + 1]);

    const float4* uv = (const float4*)(u + (size_t)n * K_DIM);
    float z[K_DIM];
    float m = -3.4e38f;
    #pragma unroll
    for (int kc = 0; kc < 8; kc++) {
        float4 uq = uv[kc];
        float ue[4] = {uq.x, uq.y, uq.z, uq.w};
        #pragma unroll
        for (int q = 0; q < 4; q++) {
            int k = kc * 4 + q;
            float lg = l[k] * scal;
            lg = (msk[k] == 0.0f) ? -1e9f : lg;
            float g = -__logf(-__logf(ue[q] + EPSF) + EPSF);
            float zz = lg + g;   // TAU = 1
            z[k] = zz;
            m = fmaxf(m, zz);
        }
    }
    float ssum = 0.0f;
    #pragma unroll
    for (int k = 0; k < K_DIM; k++) {
        float e = __expf(z[k] - m);
        z[k] = e;
        ssum += e;
    }
    float inv = 1.0f / ssum;

    float ent = 0.0f;
    float4* so = (float4*)(s_out + (size_t)n * K_DIM);
    #pragma unroll
    for (int kc = 0; kc < 8; kc++) {
        float s0 = z[kc * 4 + 0] * inv;
        float s1 = z[kc * 4 + 1] * inv;
        float s2 = z[kc * 4 + 2] * inv;
        float s3 = z[kc * 4 + 3] * inv;
        ent += s0 * __logf(s0 + EPSF) + s1 * __logf(s1 + EPSF)
             + s2 * __logf(s2 + EPSF) + s3 * __logf(s3 + EPSF);
        so[kc] = make_float4(s0, s1, s2, s3);
    }
    return ent;
}

// ---------------- kernel A: MLP + gumbel softmax (2 nodes/thread) ----------
#define AB_THREADS 128
__global__ __launch_bounds__(AB_THREADS, 4)
void hp_assign_kernel(const float* __restrict__ x,
                      const float* __restrict__ u,
                      const float* __restrict__ W1,
                      const float* __restrict__ b1,
                      const float* __restrict__ W2,
                      const float* __restrict__ b2,
                      const float* __restrict__ scaling,
                      const float* __restrict__ amask,
                      float* __restrict__ s_out,
                      int N) {
    __shared__ __align__(16) float W1s[C_DIM * C_DIM];   // [j][i]
    __shared__ __align__(16) float W2s[C_DIM * K_DIM];   // [i][k]
    __shared__ __align__(16) float b1s[C_DIM];
    __shared__ __align__(16) float b2s[K_DIM];
    __shared__ float msk[K_DIM];
    __shared__ float scal;

    int t = threadIdx.x;
    for (int i = t; i < C_DIM * C_DIM; i += AB_THREADS) W1s[i] = W1[i];
    for (int i = t; i < C_DIM * K_DIM; i += AB_THREADS) W2s[i] = W2[i];
    if (t < C_DIM) b1s[t] = b1[t];
    if (t < K_DIM) { b2s[t] = b2[t]; msk[t] = amask[t]; }
    if (t == 0) scal = scaling[0];
    __syncthreads();

    // block covers 256 nodes; thread t handles n0 = base+t and n1 = base+t+128
    int base = blockIdx.x * 256;
    int n0 = base + t;
    int n1 = n0 + AB_THREADS;
    bool v0 = n0 < N, v1 = n1 < N;

    unsigned long long lA[K_DIM / 2], lB[K_DIM / 2];
    #pragma unroll
    for (int k = 0; k < K_DIM / 2; k++) {
        unsigned long long b = pack2(b2s[2 * k], b2s[2 * k + 1]);
        lA[k] = b;
        lB[k] = b;
    }

    const float4* xa = (const float4*)(x + (size_t)n0 * C_DIM);
    const float4* xb = (const float4*)(x + (size_t)n1 * C_DIM);
    const ulonglong2* W1q = (const ulonglong2*)W1s;   // 16 u128 per row of 64
    const ulonglong2* W2q = (const ulonglong2*)W2s;   // 8 u128 per row of 32

    // 4 passes over hidden, 16 hidden units per pass
    #pragma unroll
    for (int p = 0; p < 4; p++) {
        unsigned long long hA[8], hB[8];
        #pragma unroll
        for (int m = 0; m < 8; m++) {
            unsigned long long b = pack2(b1s[p * 16 + 2 * m], b1s[p * 16 + 2 * m + 1]);
            hA[m] = b;
            hB[m] = b;
        }

        #pragma unroll
        for (int jc = 0; jc < 16; jc++) {
            float4 qa = v0 ? xa[jc] : make_float4(0.f, 0.f, 0.f, 0.f);
            float4 qb = v1 ? xb[jc] : make_float4(0.f, 0.f, 0.f, 0.f);
            float ea[4] = {qa.x, qa.y, qa.z, qa.w};
            float eb[4] = {qb.x, qb.y, qb.z, qb.w};
            #pragma unroll
            for (int q = 0; q < 4; q++) {
                int j = jc * 4 + q;
                unsigned long long a2 = pack2(ea[q], ea[q]);
                unsigned long long c2 = pack2(eb[q], eb[q]);
                const ulonglong2* row = W1q + j * 16 + p * 4;
                #pragma unroll
                for (int i4 = 0; i4 < 4; i4++) {
                    ulonglong2 w = row[i4];
                    hA[2 * i4]     = fma2(a2, w.x, hA[2 * i4]);
                    hA[2 * i4 + 1] = fma2(a2, w.y, hA[2 * i4 + 1]);
                    hB[2 * i4]     = fma2(c2, w.x, hB[2 * i4]);
                    hB[2 * i4 + 1] = fma2(c2, w.y, hB[2 * i4 + 1]);
                }
            }
        }

        // GEMM2 partial: relu(h_chunk) @ W2 rows [p*16, p*16+16)
        #pragma unroll
        for (int iu = 0; iu < 8; iu++) {
            float a0, a1, c0, c1;
            unpack2(hA[iu], a0, a1);
            unpack2(hB[iu], c0, c1);
            a0 = fmaxf(a0, 0.f); a1 = fmaxf(a1, 0.f);
            c0 = fmaxf(c0, 0.f); c1 = fmaxf(c1, 0.f);
            unsigned long long ha0 = pack2(a0, a0), ha1 = pack2(a1, a1);
            unsigned long long hb0 = pack2(c0, c0), hb1 = pack2(c1, c1);
            int i0 = p * 16 + iu * 2;
            const ulonglong2* r0 = W2q + i0 * 8;
            const ulonglong2* r1 = r0 + 8;
            #pragma unroll
            for (int k2 = 0; k2 < 8; k2++) {
                ulonglong2 w = r0[k2];
                lA[2 * k2]     = fma2(ha0, w.x, lA[2 * k2]);
                lA[2 * k2 + 1] = fma2(ha0, w.y, lA[2 * k2 + 1]);
                lB[2 * k2]     = fma2(hb0, w.x, lB[2 * k2]);
                lB[2 * k2 + 1] = fma2(hb0, w.y, lB[2 * k2 + 1]);
            }
            #pragma unroll
            for (int k2 = 0; k2 < 8; k2++) {
                ulonglong2 w = r1[k2];
                lA[2 * k2]     = fma2(ha1, w.x, lA[2 * k2]);
                lA[2 * k2 + 1] = fma2(ha1, w.y, lA[2 * k2 + 1]);
                lB[2 * k2]     = fma2(hb1, w.x, lB[2 * k2]);
                lB[2 * k2 + 1] = fma2(hb1, w.y, lB[2 * k2 + 1]);
            }
        }
    }

    float ent_local = 0.0f;
    if (v0) ent_local += hp_epilogue(lA, u, n0, scal, msk, s_out);
    if (v1) ent_local += hp_epilogue(lB, u, n1, scal, msk, s_out);

    // block-reduce entropy, one atomic per block
    #pragma unroll
    for (int o = 16; o; o >>= 1) ent_local += __shfl_xor_sync(0xffffffffu, ent_local, o);
    __shared__ float wsum[4];
    if ((t & 31) == 0) wsum[t >> 5] = ent_local;
    __syncthreads();
    if (t == 0) {
        atomicAdd(&g_ent, wsum[0] + wsum[1] + wsum[2] + wsum[3]);
    }
}

// ---------------- kernel B: pooled features + centroid sums ----------------
#define PSPLITS 64
__global__ __launch_bounds__(256)
void hp_pool_kernel(const float* __restrict__ x,
                    const float* __restrict__ pos,
                    const float* __restrict__ s,
                    float* __restrict__ out) {
    int b = blockIdx.y;
    int n0 = g_start[b], n1 = g_start[b + 1];
    int cnt = n1 - n0;
    int chunk = (cnt + PSPLITS - 1) / PSPLITS;
    int s0 = n0 + blockIdx.x * chunk;
    int s1 = min(s0 + chunk, n1);
    if (s0 >= s1) return;

    __shared__ __align__(16) float ssh[64][33];
    __shared__ __align__(16) float xsh[64][68];
    __shared__ float psh[64][2];

    int t = threadIdx.x;
    int k = t & 31;
    int grp = t >> 5;   // warp id 0..7, c-slice = grp*8..grp*8+8

    unsigned long long acc2[4];
    #pragma unroll
    for (int j = 0; j < 4; j++) acc2[j] = 0ull;
    float ass = 0.0f, apx = 0.0f, apy = 0.0f, aq = 0.0f;

    for (int tile = s0; tile < s1; tile += 64) {
        // stage s tile [64 nodes][32 k], float4 loads, scalar conflict-free stores
        for (int idx = t; idx < 64 * 8; idx += 256) {
            int node = idx >> 3, kg = idx & 7;
            int gn = tile + node;
            float4 v = (gn < s1) ? ((const float4*)(s + (size_t)gn * K_DIM))[kg]
                                 : make_float4(0.f, 0.f, 0.f, 0.f);
            ssh[node][kg * 4 + 0] = v.x;
            ssh[node][kg * 4 + 1] = v.y;
            ssh[node][kg * 4 + 2] = v.z;
            ssh[node][kg * 4 + 3] = v.w;
        }
        // stage x tile [64][64], vector stores
        for (int idx = t; idx < 64 * 16; idx += 256) {
            int node = idx >> 4, cg = idx & 15;
            int gn = tile + node;
            float4 v = (gn < s1) ? ((const float4*)(x + (size_t)gn * C_DIM))[cg]
                                 : make_float4(0.f, 0.f, 0.f, 0.f);
            *(float4*)(&xsh[node][cg * 4]) = v;
        }
        // stage pos tile
        if (t < 128) {
            int node = t >> 1, d = t & 1;
            int gn = tile + node;
            psh[node][d] = (gn < s1) ? pos[(size_t)gn * 2 + d] : 0.0f;
        }
        __syncthreads();

        #pragma unroll 8
        for (int nn = 0; nn < 64; nn++) {
            float sv = ssh[nn][k];
            unsigned long long sv2 = pack2(sv, sv);
            const ulonglong2* xr = (const ulonglong2*)(&xsh[nn][grp * 8]);
            ulonglong2 x0 = xr[0];
            acc2[0] = fma2(sv2, x0.x, acc2[0]);
            acc2[1] = fma2(sv2, x0.y, acc2[1]);
            ulonglong2 x1 = xr[1];
            acc2[2] = fma2(sv2, x1.x, acc2[2]);
            acc2[3] = fma2(sv2, x1.y, acc2[3]);
            if (grp == 0) {
                float px = psh[nn][0], py = psh[nn][1];
                ass += sv;
                apx += sv * px;
                apy += sv * py;
                aq  += sv * (px * px + py * py);
            }
        }
        __syncthreads();
    }

    float accf[8];
    #pragma unroll
    for (int j = 0; j < 4; j++) unpack2(acc2[j], accf[2 * j], accf[2 * j + 1]);
    #pragma unroll
    for (int j = 0; j < 8; j++)
        atomicAdd(&out[OFF_OUT + ((size_t)b * K_DIM + k) * C_DIM + grp * 8 + j], accf[j]);
    if (grp == 0) {
        int bk = b * K_DIM + k;
        atomicAdd(&g_ss[bk], ass);
        atomicAdd(&g_spp[2 * bk + 0], apx);
        atomicAdd(&g_spp[2 * bk + 1], apy);
        atomicAdd(&g_spq[k], aq);
    }
}

// ---------------- kernel C: finalize scalars, mu, separation ----------------
__global__ __launch_bounds__(512)
void hp_final_kernel(const float* __restrict__ amask, float* __restrict__ out, int N) {
    __shared__ float mush[B_DIM * K_DIM][2];
    __shared__ float red[16];

    const size_t off_scalars = (size_t)OFF_S + (size_t)N * K_DIM;
    const size_t OFF_ENT  = off_scalars + 0;
    const size_t OFF_DIV  = off_scalars + 1;
    const size_t OFF_SPAT = off_scalars + 2;
    const size_t OFF_PRUN = off_scalars + 3;
    const size_t OFF_SPAR = off_scalars + 4;
    const size_t OFF_SEP  = off_scalars + 5;
    const size_t OFF_MU   = off_scalars + 6;

    int t = threadIdx.x;        // 512 = B*K
    int bk = t;
    float ssv = g_ss[bk];
    float denom = ssv + EPSF;
    float mux = g_spp[2 * bk] / denom;
    float muy = g_spp[2 * bk + 1] / denom;
    mush[bk][0] = mux;
    mush[bk][1] = muy;
    out[OFF_MU + 2 * bk] = mux;
    out[OFF_MU + 2 * bk + 1] = muy;
    __syncthreads();

    int b = bk >> 5, k1 = bk & 31;
    float sep = 0.0f;
    #pragma unroll
    for (int k2 = 0; k2 < K_DIM; k2++) {
        if (k2 == k1) continue;
        float dx = mux - mush[b * K_DIM + k2][0];
        float dy = muy - mush[b * K_DIM + k2][1];
        sep += 1.0f / (dx * dx + dy * dy + 1.0f);
    }
    #pragma unroll
    for (int o = 16; o; o >>= 1) sep += __shfl_xor_sync(0xffffffffu, sep, o);
    if ((t & 31) == 0) red[t >> 5] = sep;
    __syncthreads();

    if (t == 0) {
        float tot = 0.0f;
        for (int i = 0; i < 16; i++) tot += red[i];
        out[OFF_SEP] = tot / ((float)(K_DIM * (K_DIM - 1)) + EPSF);

        float div = 0.0f, spat = 0.0f, prun = 0.0f, spars = 0.0f;
        for (int k = 0; k < K_DIM; k++) {
            float ss = 0.0f, sx = 0.0f, sy = 0.0f;
            for (int bb = 0; bb < B_DIM; bb++) {
                int idx = bb * K_DIM + k;
                ss += g_ss[idx];
                sx += g_spp[2 * idx];
                sy += g_spp[2 * idx + 1];
            }
            float avg = ss / (float)N;
            div += avg * __logf(avg + EPSF);
            float sse = ss + EPSF;
            float mgx = sx / sse, mgy = sy / sse;
            float var = g_spq[k] / sse
                        - 2.0f * (mgx * (sx / sse) + mgy * (sy / sse))
                        + (mgx * mgx + mgy * mgy);
            spat += var;
            float mk = amask[k];
            prun += fabsf(avg * (1.0f - mk));
            spars += mk;
        }
        out[OFF_ENT]  = -g_ent / (float)N;
        out[OFF_DIV]  = div;
        out[OFF_SPAT] = spat / (float)K_DIM;
        out[OFF_PRUN] = prun / (float)K_DIM;
        out[OFF_SPAR] = spars / (float)K_DIM;
    }
}

// ---------------- launcher ----------------
extern "C" void kernel_launch(void* const* d_in, const int* in_sizes, int n_in,
                              void* d_out, int out_size) {
    (void)n_in; (void)out_size;
    const float* x       = (const float*)d_in[0];
    const int*   batch   = (const int*)d_in[1];
    const float* pos     = (const float*)d_in[2];
    const float* u       = (const float*)d_in[3];
    const float* W1      = (const float*)d_in[4];
    const float* b1      = (const float*)d_in[5];
    const float* W2      = (const float*)d_in[6];
    const float* b2      = (const float*)d_in[7];
    const float* scaling = (const float*)d_in[8];
    const float* amask   = (const float*)d_in[9];
    float* out = (float*)d_out;

    int N = in_sizes[0] / C_DIM;

    hp_zero_kernel<<<64, 256>>>(out, N);
    hp_bound_kernel<<<256, 256>>>(batch, N);
    hp_fix_kernel<<<1, 1>>>(N);
    hp_assign_kernel<<<(N + 255) / 256, AB_THREADS>>>(x, u, W1, b1, W2, b2, scaling,
                                                      amask, out + OFF_S, N);
    hp_pool_kernel<<<dim3(PSPLITS, B_DIM), 256>>>(x, pos, out + OFF_S, out);
    hp_final_kernel<<<1, 512>>>(amask, out, N);
}

// round 4
// speedup vs baseline: 1.0693x; 1.0662x over previous
#include <cuda_runtime.h>
#include <cuda_bf16.h>
#include <cstdint>

typedef unsigned long long ull;

#define C_DIM 64
#define K_DIM 32
#define B_DIM 16
#define EPSF  1e-9f
#define MAXN  131072

// Output layout: out[B,K,C]=32768 | s[N,K] | entropy, diversity, spatial,
// pruning, sparsity, separation | mu[B,K,2]
#define OFF_OUT   0
#define OUT_ELEMS (B_DIM * K_DIM * C_DIM)
#define OFF_S     OUT_ELEMS

// ---------------- device scratch ----------------
__device__ float g_h[(size_t)MAXN * C_DIM];   // hidden activations (32MB)
__device__ float g_ent;
__device__ float g_ss[B_DIM * K_DIM];
__device__ float g_spp[B_DIM * K_DIM * 2];
__device__ float g_spq[K_DIM];
__device__ int   g_start[B_DIM + 1];

// ---------------- packed f32x2 helpers ----------------
__device__ __forceinline__ ull pack2(float lo, float hi) {
    ull r;
    asm("mov.b64 %0, {%1, %2};" : "=l"(r) : "f"(lo), "f"(hi));
    return r;
}
__device__ __forceinline__ void unpack2(ull v, float& lo, float& hi) {
    asm("mov.b64 {%0, %1}, %2;" : "=f"(lo), "=f"(hi) : "l"(v));
}
__device__ __forceinline__ ull fma2(ull a, ull b, ull c) {
    ull d;
    asm("fma.rn.f32x2 %0, %1, %2, %3;" : "=l"(d) : "l"(a), "l"(b), "l"(c));
    return d;
}

// ---------------- kernel 0: zero ----------------
__global__ void hp_zero_kernel(float* __restrict__ out, int N) {
    int i = blockIdx.x * blockDim.x + threadIdx.x;
    int stride = gridDim.x * blockDim.x;
    for (int j = i; j < OUT_ELEMS; j += stride) out[j] = 0.0f;
    for (int j = i; j < B_DIM * K_DIM; j += stride) {
        g_ss[j] = 0.0f;
        g_spp[2 * j] = 0.0f;
        g_spp[2 * j + 1] = 0.0f;
    }
    if (i < K_DIM) g_spq[i] = 0.0f;
    if (i == 0) g_ent = 0.0f;
    if (i <= B_DIM) g_start[i] = N;
}

// ---------------- kernel 1: graph boundaries ----------------
__global__ void hp_bound_kernel(const int* __restrict__ batch, int N) {
    int n = blockIdx.x * blockDim.x + threadIdx.x;
    int stride = gridDim.x * blockDim.x;
    for (; n < N; n += stride) {
        if (n == 0 || batch[n] != batch[n - 1]) {
            atomicMin(&g_start[batch[n]], n);
        }
    }
}
__global__ void hp_fix_kernel(int N) {
    g_start[B_DIM] = N;
    for (int b = B_DIM - 1; b >= 0; b--)
        if (g_start[b] > g_start[b + 1]) g_start[b] = g_start[b + 1];
}

// ---------------- kernel A1: h = relu(x @ W1 + b1) ----------------
// block 256 thr, 128-node tile. thread tile 4 nodes x 8 hidden (split 4+4).
__global__ __launch_bounds__(256)
void hp_gemm1(const float* __restrict__ x, const float* __restrict__ W1,
              const float* __restrict__ b1, int N) {
    __shared__ float xT[64 * 128];   // [ch][node]
    __shared__ float W1s[64 * 64];   // [ch][h]
    __shared__ float b1s[64];

    int t = threadIdx.x;
    int base = blockIdx.x * 128;

    for (int i = t; i < 4096; i += 256) W1s[i] = W1[i];
    if (t < 64) b1s[t] = b1[t];
    {
        int node = t & 127, half = t >> 7;
        int gn = base + node;
        const float4* xg = (const float4*)(x + (size_t)gn * C_DIM + half * 32);
        #pragma unroll
        for (int j = 0; j < 8; j++) {
            float4 v = (gn < N) ? xg[j] : make_float4(0.f, 0.f, 0.f, 0.f);
            int ch = half * 32 + j * 4;
            xT[(ch + 0) * 128 + node] = v.x;
            xT[(ch + 1) * 128 + node] = v.y;
            xT[(ch + 2) * 128 + node] = v.z;
            xT[(ch + 3) * 128 + node] = v.w;
        }
    }
    __syncthreads();

    int ng = t >> 3;   // 0..31 -> nodes ng*4..+4
    int hg = t & 7;    // h cols: hg*4..+4 and 32+hg*4..+4

    ull acc[4][4];
    {
        float4 ba = *(float4*)&b1s[hg * 4];
        float4 bb = *(float4*)&b1s[32 + hg * 4];
        #pragma unroll
        for (int n = 0; n < 4; n++) {
            acc[n][0] = pack2(ba.x, ba.y);
            acc[n][1] = pack2(ba.z, ba.w);
            acc[n][2] = pack2(bb.x, bb.y);
            acc[n][3] = pack2(bb.z, bb.w);
        }
    }

    #pragma unroll 4
    for (int k = 0; k < 64; k++) {
        float4 xv = *(float4*)&xT[k * 128 + ng * 4];
        float4 wa = *(float4*)&W1s[k * 64 + hg * 4];
        float4 wb = *(float4*)&W1s[k * 64 + 32 + hg * 4];
        ull wa0 = pack2(wa.x, wa.y), wa1 = pack2(wa.z, wa.w);
        ull wb0 = pack2(wb.x, wb.y), wb1 = pack2(wb.z, wb.w);
        float xe[4] = {xv.x, xv.y, xv.z, xv.w};
        #pragma unroll
        for (int n = 0; n < 4; n++) {
            ull x2 = pack2(xe[n], xe[n]);
            acc[n][0] = fma2(x2, wa0, acc[n][0]);
            acc[n][1] = fma2(x2, wa1, acc[n][1]);
            acc[n][2] = fma2(x2, wb0, acc[n][2]);
            acc[n][3] = fma2(x2, wb1, acc[n][3]);
        }
    }

    #pragma unroll
    for (int n = 0; n < 4; n++) {
        int node = base + ng * 4 + n;
        if (node >= N) break;
        float a0, a1, a2, a3, c0, c1, c2, c3;
        unpack2(acc[n][0], a0, a1);
        unpack2(acc[n][1], a2, a3);
        unpack2(acc[n][2], c0, c1);
        unpack2(acc[n][3], c2, c3);
        float* hp = g_h + (size_t)node * C_DIM;
        *(float4*)(hp + hg * 4) =
            make_float4(fmaxf(a0, 0.f), fmaxf(a1, 0.f), fmaxf(a2, 0.f), fmaxf(a3, 0.f));
        *(float4*)(hp + 32 + hg * 4) =
            make_float4(fmaxf(c0, 0.f), fmaxf(c1, 0.f), fmaxf(c2, 0.f), fmaxf(c3, 0.f));
    }
}

// ---------------- kernel A2: logits + gumbel softmax -> s, entropy --------
// block 256 thr, 128-node tile. thread tile 4 nodes x 4 k.
__global__ __launch_bounds__(256)
void hp_gemm2(const float* __restrict__ u, const float* __restrict__ W2,
              const float* __restrict__ b2, const float* __restrict__ scaling,
              const float* __restrict__ amask, float* __restrict__ s_out, int N) {
    __shared__ float hT[64 * 128];     // [hid][node]
    __shared__ float W2s[64 * 32];     // [hid][k]
    __shared__ float b2s[32], msk[32];
    __shared__ float lsh[128 * 36];    // logits [node][k], padded
    __shared__ float scal_s;
    __shared__ float wsum[8];

    int t = threadIdx.x;
    int base = blockIdx.x * 128;

    for (int i = t; i < 2048; i += 256) W2s[i] = W2[i];
    if (t < 32) { b2s[t] = b2[t]; msk[t] = amask[t]; }
    if (t == 0) scal_s = scaling[0];
    {
        int node = t & 127, half = t >> 7;
        int gn = base + node;
        const float4* hg4 = (const float4*)(g_h + (size_t)gn * C_DIM + half * 32);
        #pragma unroll
        for (int j = 0; j < 8; j++) {
            float4 v = (gn < N) ? hg4[j] : make_float4(0.f, 0.f, 0.f, 0.f);
            int ch = half * 32 + j * 4;
            hT[(ch + 0) * 128 + node] = v.x;
            hT[(ch + 1) * 128 + node] = v.y;
            hT[(ch + 2) * 128 + node] = v.z;
            hT[(ch + 3) * 128 + node] = v.w;
        }
    }
    __syncthreads();

    int ng = t >> 3;   // 0..31
    int kg = t & 7;    // k cols kg*4..+4

    ull acc[4][2];
    {
        float4 bb = *(float4*)&b2s[kg * 4];
        #pragma unroll
        for (int n = 0; n < 4; n++) {
            acc[n][0] = pack2(bb.x, bb.y);
            acc[n][1] = pack2(bb.z, bb.w);
        }
    }

    #pragma unroll 4
    for (int h = 0; h < 64; h++) {
        float4 hv = *(float4*)&hT[h * 128 + ng * 4];
        float4 wv = *(float4*)&W2s[h * 32 + kg * 4];
        ull w0 = pack2(wv.x, wv.y), w1 = pack2(wv.z, wv.w);
        float he[4] = {hv.x, hv.y, hv.z, hv.w};
        #pragma unroll
        for (int n = 0; n < 4; n++) {
            ull x2 = pack2(he[n], he[n]);
            acc[n][0] = fma2(x2, w0, acc[n][0]);
            acc[n][1] = fma2(x2, w1, acc[n][1]);
        }
    }

    #pragma unroll
    for (int n = 0; n < 4; n++) {
        float l0, l1, l2, l3;
        unpack2(acc[n][0], l0, l1);
        unpack2(acc[n][1], l2, l3);
        *(float4*)&lsh[(ng * 4 + n) * 36 + kg * 4] = make_float4(l0, l1, l2, l3);
    }
    __syncthreads();

    // epilogue: one node per thread (threads 0..127)
    float ent_local = 0.0f;
    if (t < 128 && base + t < N) {
        int n = base + t;
        float scal = scal_s;
        float l[K_DIM];
        #pragma unroll
        for (int j = 0; j < 8; j++) {
            float4 v = *(float4*)&lsh[t * 36 + j * 4];
            l[4 * j + 0] = v.x; l[4 * j + 1] = v.y;
            l[4 * j + 2] = v.z; l[4 * j + 3] = v.w;
        }
        const float4* uv = (const float4*)(u + (size_t)n * K_DIM);
        float z[K_DIM];
        float m = -3.4e38f;
        #pragma unroll
        for (int kc = 0; kc < 8; kc++) {
            float4 uq = uv[kc];
            float ue[4] = {uq.x, uq.y, uq.z, uq.w};
            #pragma unroll
            for (int q = 0; q < 4; q++) {
                int k = kc * 4 + q;
                float lg = l[k] * scal;
                lg = (msk[k] == 0.0f) ? -1e9f : lg;
                float g = -__logf(-__logf(ue[q] + EPSF) + EPSF);
                float zz = lg + g;   // TAU = 1
                z[k] = zz;
                m = fmaxf(m, zz);
            }
        }
        float ssum = 0.0f;
        #pragma unroll
        for (int k = 0; k < K_DIM; k++) {
            float e = __expf(z[k] - m);
            z[k] = e;
            ssum += e;
        }
        float inv = 1.0f / ssum;
        float4* so = (float4*)(s_out + (size_t)n * K_DIM);
        #pragma unroll
        for (int kc = 0; kc < 8; kc++) {
            float s0 = z[kc * 4 + 0] * inv;
            float s1 = z[kc * 4 + 1] * inv;
            float s2 = z[kc * 4 + 2] * inv;
            float s3 = z[kc * 4 + 3] * inv;
            ent_local += s0 * __logf(s0 + EPSF) + s1 * __logf(s1 + EPSF)
                       + s2 * __logf(s2 + EPSF) + s3 * __logf(s3 + EPSF);
            so[kc] = make_float4(s0, s1, s2, s3);
        }
    }

    #pragma unroll
    for (int o = 16; o; o >>= 1) ent_local += __shfl_xor_sync(0xffffffffu, ent_local, o);
    if ((t & 31) == 0) wsum[t >> 5] = ent_local;
    __syncthreads();
    if (t == 0) {
        float w = 0.f;
        #pragma unroll
        for (int i = 0; i < 8; i++) w += wsum[i];
        atomicAdd(&g_ent, w);
    }
}

// ---------------- kernel B: pooled features (s^T @ x per graph) -----------
#define PSPL 32
__global__ __launch_bounds__(256)
void hp_pool(const float* __restrict__ x, const float* __restrict__ s,
             float* __restrict__ out) {
    int b = blockIdx.y;
    int n0 = g_start[b], n1 = g_start[b + 1];
    int cnt = n1 - n0;
    int chunk = (cnt + PSPL - 1) / PSPL;
    int s0 = n0 + blockIdx.x * chunk;
    int s1 = min(s0 + chunk, n1);
    if (s0 >= s1) return;

    __shared__ float ssh[64 * 36];   // [node][k] padded
    __shared__ float xsh[64 * 68];   // [node][c] padded

    int t = threadIdx.x;
    int wc = t >> 5;        // warp id 0..7 -> c block wc*8
    int lane = t & 31;
    int kq = lane >> 2;     // k tile kq*4..+4
    int cq = lane & 3;      // c sub cq*2..+2

    ull acc2[4] = {0ull, 0ull, 0ull, 0ull};

    for (int tile = s0; tile < s1; tile += 64) {
        for (int idx = t; idx < 64 * 8; idx += 256) {
            int node = idx >> 3, kp = idx & 7;
            int gn = tile + node;
            float4 v = (gn < s1) ? ((const float4*)(s + (size_t)gn * K_DIM))[kp]
                                 : make_float4(0.f, 0.f, 0.f, 0.f);
            *(float4*)&ssh[node * 36 + kp * 4] = v;
        }
        for (int idx = t; idx < 64 * 16; idx += 256) {
            int node = idx >> 4, cg = idx & 15;
            int gn = tile + node;
            float4 v = (gn < s1) ? ((const float4*)(x + (size_t)gn * C_DIM))[cg]
                                 : make_float4(0.f, 0.f, 0.f, 0.f);
            *(float4*)&xsh[node * 68 + cg * 4] = v;
        }
        __syncthreads();

        #pragma unroll 4
        for (int nn = 0; nn < 64; nn++) {
            float4 sv = *(float4*)&ssh[nn * 36 + kq * 4];
            ull xv = *(const ull*)&xsh[nn * 68 + wc * 8 + cq * 2];
            acc2[0] = fma2(pack2(sv.x, sv.x), xv, acc2[0]);
            acc2[1] = fma2(pack2(sv.y, sv.y), xv, acc2[1]);
            acc2[2] = fma2(pack2(sv.z, sv.z), xv, acc2[2]);
            acc2[3] = fma2(pack2(sv.w, sv.w), xv, acc2[3]);
        }
        __syncthreads();
    }

    int cbase = wc * 8 + cq * 2;
    #pragma unroll
    for (int kk = 0; kk < 4; kk++) {
        float v0, v1;
        unpack2(acc2[kk], v0, v1);
        int k = kq * 4 + kk;
        atomicAdd(&out[(size_t)b * K_DIM * C_DIM + (size_t)k * C_DIM + cbase + 0], v0);
        atomicAdd(&out[(size_t)b * K_DIM * C_DIM + (size_t)k * C_DIM + cbase + 1], v1);
    }
}

// ---------------- kernel B2: centroid moment sums --------------------------
__global__ __launch_bounds__(256)
void hp_moment(const float* __restrict__ s, const float* __restrict__ pos) {
    int b = blockIdx.y;
    int n0 = g_start[b], n1 = g_start[b + 1];
    int cnt = n1 - n0;
    int st = blockIdx.x * 8 + (threadIdx.x >> 5);   // stripe 0..63
    int lane = threadIdx.x & 31;                    // = k
    int chunk = (cnt + 63) / 64;
    int a = n0 + st * chunk;
    int e = min(a + chunk, n1);
    if (a >= e) return;

    float ss = 0.f, apx = 0.f, apy = 0.f, aq = 0.f;
    for (int n = a; n < e; n++) {
        float sv = s[(size_t)n * K_DIM + lane];
        float2 p = *(const float2*)(pos + 2 * (size_t)n);
        ss += sv;
        apx += sv * p.x;
        apy += sv * p.y;
        aq  += sv * (p.x * p.x + p.y * p.y);
    }
    int bk = b * K_DIM + lane;
    atomicAdd(&g_ss[bk], ss);
    atomicAdd(&g_spp[2 * bk + 0], apx);
    atomicAdd(&g_spp[2 * bk + 1], apy);
    atomicAdd(&g_spq[lane], aq);
}

// ---------------- kernel C: finalize ----------------
__global__ __launch_bounds__(512)
void hp_final_kernel(const float* __restrict__ amask, float* __restrict__ out, int N) {
    __shared__ float mush[B_DIM * K_DIM][2];
    __shared__ float red[16];

    const size_t off_scalars = (size_t)OFF_S + (size_t)N * K_DIM;
    const size_t OFF_ENT  = off_scalars + 0;
    const size_t OFF_DIV  = off_scalars + 1;
    const size_t OFF_SPAT = off_scalars + 2;
    const size_t OFF_PRUN = off_scalars + 3;
    const size_t OFF_SPAR = off_scalars + 4;
    const size_t OFF_SEP  = off_scalars + 5;
    const size_t OFF_MU   = off_scalars + 6;

    int t = threadIdx.x;
    int bk = t;
    float ssv = g_ss[bk];
    float denom = ssv + EPSF;
    float mux = g_spp[2 * bk] / denom;
    float muy = g_spp[2 * bk + 1] / denom;
    mush[bk][0] = mux;
    mush[bk][1] = muy;
    out[OFF_MU + 2 * bk] = mux;
    out[OFF_MU + 2 * bk + 1] = muy;
    __syncthreads();

    int b = bk >> 5, k1 = bk & 31;
    float sep = 0.0f;
    #pragma unroll
    for (int k2 = 0; k2 < K_DIM; k2++) {
        if (k2 == k1) continue;
        float dx = mux - mush[b * K_DIM + k2][0];
        float dy = muy - mush[b * K_DIM + k2][1];
        sep += 1.0f / (dx * dx + dy * dy + 1.0f);
    }
    #pragma unroll
    for (int o = 16; o; o >>= 1) sep += __shfl_xor_sync(0xffffffffu, sep, o);
    if ((t & 31) == 0) red[t >> 5] = sep;
    __syncthreads();

    if (t == 0) {
        float tot = 0.0f;
        for (int i = 0; i < 16; i++) tot += red[i];
        out[OFF_SEP] = tot / ((float)(K_DIM * (K_DIM - 1)) + EPSF);

        float div = 0.0f, spat = 0.0f, prun = 0.0f, spars = 0.0f;
        for (int k = 0; k < K_DIM; k++) {
            float ss = 0.0f, sx = 0.0f, sy = 0.0f;
            for (int bb = 0; bb < B_DIM; bb++) {
                int idx = bb * K_DIM + k;
                ss += g_ss[idx];
                sx += g_spp[2 * idx];
                sy += g_spp[2 * idx + 1];
            }
            float avg = ss / (float)N;
            div += avg * __logf(avg + EPSF);
            float sse = ss + EPSF;
            float mgx = sx / sse, mgy = sy / sse;
            float var = g_spq[k] / sse
                        - 2.0f * (mgx * (sx / sse) + mgy * (sy / sse))
                        + (mgx * mgx + mgy * mgy);
            spat += var;
            float mk = amask[k];
            prun += fabsf(avg * (1.0f - mk));
            spars += mk;
        }
        out[OFF_ENT]  = -g_ent / (float)N;
        out[OFF_DIV]  = div;
        out[OFF_SPAT] = spat / (float)K_DIM;
        out[OFF_PRUN] = prun / (float)K_DIM;
        out[OFF_SPAR] = spars / (float)K_DIM;
    }
}

// ---------------- launcher ----------------
extern "C" void kernel_launch(void* const* d_in, const int* in_sizes, int n_in,
                              void* d_out, int out_size) {
    (void)n_in; (void)out_size;
    const float* x       = (const float*)d_in[0];
    const int*   batch   = (const int*)d_in[1];
    const float* pos     = (const float*)d_in[2];
    const float* u       = (const float*)d_in[3];
    const float* W1      = (const float*)d_in[4];
    const float* b1      = (const float*)d_in[5];
    const float* W2      = (const float*)d_in[6];
    const float* b2      = (const float*)d_in[7];
    const float* scaling = (const float*)d_in[8];
    const float* amask   = (const float*)d_in[9];
    float* out = (float*)d_out;

    int N = in_sizes[0] / C_DIM;
    int gtiles = (N + 127) / 128;

    hp_zero_kernel<<<64, 256>>>(out, N);
    hp_bound_kernel<<<256, 256>>>(batch, N);
    hp_fix_kernel<<<1, 1>>>(N);
    hp_gemm1<<<gtiles, 256>>>(x, W1, b1, N);
    hp_gemm2<<<gtiles, 256>>>(u, W2, b2, scaling, amask, out + OFF_S, N);
    hp_pool<<<dim3(PSPL, B_DIM), 256>>>(x, out + OFF_S, out);
    hp_moment<<<dim3(8, B_DIM), 256>>>(out + OFF_S, pos);
    hp_final_kernel<<<1, 512>>>(amask, out, N);
}

// round 6
// speedup vs baseline: 1.3381x; 1.2515x over previous
#include <cuda_runtime.h>
#include <cuda_bf16.h>
#include <cstdint>

typedef unsigned long long ull;

#define C_DIM 64
#define K_DIM 32
#define B_DIM 16
#define EPSF  1e-9f

// Output layout: out[B,K,C]=32768 | s[N,K] | entropy, diversity, spatial,
// pruning, sparsity, separation | mu[B,K,2]
#define OFF_OUT   0
#define OUT_ELEMS (B_DIM * K_DIM * C_DIM)
#define OFF_S     OUT_ELEMS

// ---------------- device scratch ----------------
__device__ float g_ent;
__device__ float g_ss[B_DIM * K_DIM];
__device__ float g_spp[B_DIM * K_DIM * 2];
__device__ float g_spq[K_DIM];

// ---------------- packed f32x2 helpers ----------------
__device__ __forceinline__ ull pack2(float lo, float hi) {
    ull r;
    asm("mov.b64 %0, {%1, %2};" : "=l"(r) : "f"(lo), "f"(hi));
    return r;
}
__device__ __forceinline__ void unpack2(ull v, float& lo, float& hi) {
    asm("mov.b64 {%0, %1}, %2;" : "=f"(lo), "=f"(hi) : "l"(v));
}
__device__ __forceinline__ ull fma2(ull a, ull b, ull c) {
    ull d;
    asm("fma.rn.f32x2 %0, %1, %2, %3;" : "=l"(d) : "l"(a), "l"(b), "l"(c));
    return d;
}

// ---------------- smem layout (floats) ----------------
// lsh stride MUST be a multiple of 4 floats (16B) for float4 row access.
#define LSTR 36
#define OFF_XT   0        // [64][132] xT[ch][node]; later pool-tree scratch
#define OFF_HT   8448     // [64][132] hT[h][node]; also GEMM1 k-split scratch
#define OFF_W1   16896    // [64][64]
#define OFF_W2   20992    // [64][32]
#define OFF_LSH  23040    // [128][36] logits/s rows; also GEMM2 scratch [32][132]
#define OFF_PSH  27648    // [128][2]
#define OFF_B1   27904    // 64
#define OFF_B2   27968    // 32
#define OFF_MSK  28000    // 32
#define OFF_SCAL 28032    // 1
#define OFF_WSUM 28033    // 8
#define OFF_BSH  28044    // 128 ints
#define SMEM_FLOATS 28172
#define SMEM_BYTES  (SMEM_FLOATS * 4)

// ---------------- kernel 0: zero ----------------
__global__ void hp_zero_kernel(float* __restrict__ out) {
    int i = blockIdx.x * blockDim.x + threadIdx.x;
    int stride = gridDim.x * blockDim.x;
    for (int j = i; j < OUT_ELEMS; j += stride) out[j] = 0.0f;
    for (int j = i; j < B_DIM * K_DIM; j += stride) {
        g_ss[j] = 0.0f;
        g_spp[2 * j] = 0.0f;
        g_spp[2 * j + 1] = 0.0f;
    }
    if (i < K_DIM) g_spq[i] = 0.0f;
    if (i == 0) g_ent = 0.0f;
}

// ---------------- fused kernel: MLP + softmax + pool + moments -------------
__global__ __launch_bounds__(256, 2)
void hp_fused(const float* __restrict__ x, const int* __restrict__ batch,
              const float* __restrict__ pos, const float* __restrict__ u,
              const float* __restrict__ W1, const float* __restrict__ b1,
              const float* __restrict__ W2, const float* __restrict__ b2,
              const float* __restrict__ scaling, const float* __restrict__ amask,
              float* __restrict__ out, float* __restrict__ s_out, int N) {
    extern __shared__ float sm[];
    float* xT  = sm + OFF_XT;
    float* hT  = sm + OFF_HT;
    float* W1s = sm + OFF_W1;
    float* W2s = sm + OFF_W2;
    float* lsh = sm + OFF_LSH;
    float* psh = sm + OFF_PSH;
    float* b1s = sm + OFF_B1;
    float* b2s = sm + OFF_B2;
    float* msk = sm + OFF_MSK;
    float* wsum = sm + OFF_WSUM;
    int*   bsh = (int*)(sm + OFF_BSH);

    const int t = threadIdx.x;
    const int base = blockIdx.x * 128;

    // ================= stage =================
    for (int i = t; i < 4096; i += 256) W1s[i] = W1[i];
    for (int i = t; i < 2048; i += 256) W2s[i] = W2[i];
    if (t < 64) b1s[t] = b1[t];
    if (t < 32) { b2s[t] = b2[t]; msk[t] = amask[t]; }
    if (t == 0) sm[OFF_SCAL] = scaling[0];
    {
        int node = t & 127, half = t >> 7;
        int gn = base + node;
        int gcl = min(gn, N - 1);
        bool v = gn < N;
        const float4* xg = (const float4*)(x + (size_t)gcl * C_DIM + half * 32);
        #pragma unroll
        for (int j = 0; j < 8; j++) {
            float4 q = v ? xg[j] : make_float4(0.f, 0.f, 0.f, 0.f);
            int ch = half * 32 + j * 4;
            xT[(ch + 0) * 132 + node] = q.x;
            xT[(ch + 1) * 132 + node] = q.y;
            xT[(ch + 2) * 132 + node] = q.z;
            xT[(ch + 3) * 132 + node] = q.w;
        }
        if (half == 0) {
            bsh[node] = batch[gcl];
            float2 p = v ? *(const float2*)(pos + 2 * (size_t)gn)
                         : make_float2(0.f, 0.f);
            psh[node * 2] = p.x;
            psh[node * 2 + 1] = p.y;
        }
    }
    __syncthreads();

    const int t7 = t & 127, ksp = t >> 7;

    // ================= GEMM1: h = relu(x@W1+b1) =================
    {
        const int ng = t7 >> 3;   // 0..15 -> nodes ng*8..+8
        const int hg = t7 & 7;    // h cols hg*8..+8
        ull acc[32];
        #pragma unroll
        for (int i = 0; i < 32; i++) acc[i] = 0ull;
        const int k0 = ksp * 32;
        #pragma unroll 4
        for (int k = 0; k < 32; k++) {
            const float* xr = &xT[(k0 + k) * 132 + ng * 8];
            float4 xa = *(const float4*)xr;
            float4 xb = *(const float4*)(xr + 4);
            const float* wr = &W1s[(k0 + k) * 64 + hg * 8];
            float4 wa = *(const float4*)wr;
            float4 wb = *(const float4*)(wr + 4);
            ull w0 = pack2(wa.x, wa.y), w1p = pack2(wa.z, wa.w);
            ull w2p = pack2(wb.x, wb.y), w3p = pack2(wb.z, wb.w);
            float xe[8] = {xa.x, xa.y, xa.z, xa.w, xb.x, xb.y, xb.z, xb.w};
            #pragma unroll
            for (int n = 0; n < 8; n++) {
                ull x2 = pack2(xe[n], xe[n]);
                acc[n * 4 + 0] = fma2(x2, w0, acc[n * 4 + 0]);
                acc[n * 4 + 1] = fma2(x2, w1p, acc[n * 4 + 1]);
                acc[n * 4 + 2] = fma2(x2, w2p, acc[n * 4 + 2]);
                acc[n * 4 + 3] = fma2(x2, w3p, acc[n * 4 + 3]);
            }
        }
        // k-split reduce via column scratch in hT
        if (ksp == 1) {
            #pragma unroll
            for (int a = 0; a < 32; a++) {
                float lo, hi;
                unpack2(acc[a], lo, hi);
                hT[(2 * a + 0) * 132 + t7] = lo;
                hT[(2 * a + 1) * 132 + t7] = hi;
            }
        }
        __syncthreads();
        if (ksp == 0) {
            #pragma unroll
            for (int a = 0; a < 32; a++) {
                int p = a & 3;
                float lo, hi;
                unpack2(acc[a], lo, hi);
                lo += hT[(2 * a + 0) * 132 + t7] + b1s[hg * 8 + 2 * p];
                hi += hT[(2 * a + 1) * 132 + t7] + b1s[hg * 8 + 2 * p + 1];
                acc[a] = pack2(fmaxf(lo, 0.f), fmaxf(hi, 0.f));
            }
        }
        __syncthreads();
        if (ksp == 0) {
            #pragma unroll
            for (int p = 0; p < 4; p++) {
                float lo[8], hi[8];
                #pragma unroll
                for (int n = 0; n < 8; n++) unpack2(acc[n * 4 + p], lo[n], hi[n]);
                int h0 = hg * 8 + 2 * p;
                float* r0 = &hT[h0 * 132 + ng * 8];
                *(float4*)r0 = make_float4(lo[0], lo[1], lo[2], lo[3]);
                *(float4*)(r0 + 4) = make_float4(lo[4], lo[5], lo[6], lo[7]);
                float* r1 = r0 + 132;
                *(float4*)r1 = make_float4(hi[0], hi[1], hi[2], hi[3]);
                *(float4*)(r1 + 4) = make_float4(hi[4], hi[5], hi[6], hi[7]);
            }
        }
        __syncthreads();
    }

    // ================= GEMM2: logits = h@W2+b2 =================
    {
        const int ng2 = t7 >> 3;  // nodes ng2*8..+8
        const int kg = t7 & 7;    // k cols kg*4..+4
        ull acc[16];
        #pragma unroll
        for (int i = 0; i < 16; i++) acc[i] = 0ull;
        const int h0 = ksp * 32;
        #pragma unroll 4
        for (int h = 0; h < 32; h++) {
            const float* hr = &hT[(h0 + h) * 132 + ng2 * 8];
            float4 ha = *(const float4*)hr;
            float4 hb = *(const float4*)(hr + 4);
            float4 wv = *(const float4*)&W2s[(h0 + h) * 32 + kg * 4];
            ull w0 = pack2(wv.x, wv.y), w1p = pack2(wv.z, wv.w);
            float he[8] = {ha.x, ha.y, ha.z, ha.w, hb.x, hb.y, hb.z, hb.w};
            #pragma unroll
            for (int n = 0; n < 8; n++) {
                ull h2 = pack2(he[n], he[n]);
                acc[n * 2 + 0] = fma2(h2, w0, acc[n * 2 + 0]);
                acc[n * 2 + 1] = fma2(h2, w1p, acc[n * 2 + 1]);
            }
        }
        if (ksp == 1) {
            #pragma unroll
            for (int a = 0; a < 16; a++) {
                float lo, hi;
                unpack2(acc[a], lo, hi);
                lsh[(2 * a + 0) * 132 + t7] = lo;
                lsh[(2 * a + 1) * 132 + t7] = hi;
            }
        }
        __syncthreads();
        if (ksp == 0) {
            #pragma unroll
            for (int a = 0; a < 16; a++) {
                int q = a & 1;
                float lo, hi;
                unpack2(acc[a], lo, hi);
                lo += lsh[(2 * a + 0) * 132 + t7] + b2s[kg * 4 + 2 * q];
                hi += lsh[(2 * a + 1) * 132 + t7] + b2s[kg * 4 + 2 * q + 1];
                acc[a] = pack2(lo, hi);
            }
        }
        __syncthreads();
        if (ksp == 0) {
            #pragma unroll
            for (int n = 0; n < 8; n++) {
                int node = ng2 * 8 + n;
                float l0, l1, l2, l3;
                unpack2(acc[n * 2 + 0], l0, l1);
                unpack2(acc[n * 2 + 1], l2, l3);
                *(float4*)&lsh[node * LSTR + kg * 4] = make_float4(l0, l1, l2, l3);
            }
        }
        __syncthreads();
    }

    // ================= epilogue: gumbel softmax -> s =================
    float ent_local = 0.0f;
    if (t < 128) {
        int n = base + t;
        if (n < N) {
            float scal = sm[OFF_SCAL];
            float l[K_DIM];
            #pragma unroll
            for (int j = 0; j < 8; j++) {
                float4 v = *(float4*)&lsh[t * LSTR + j * 4];
                l[4 * j + 0] = v.x; l[4 * j + 1] = v.y;
                l[4 * j + 2] = v.z; l[4 * j + 3] = v.w;
            }
            const float4* uv = (const float4*)(u + (size_t)n * K_DIM);
            float z[K_DIM];
            float m = -3.4e38f;
            #pragma unroll
            for (int kc = 0; kc < 8; kc++) {
                float4 uq = uv[kc];
                float ue[4] = {uq.x, uq.y, uq.z, uq.w};
                #pragma unroll
                for (int q = 0; q < 4; q++) {
                    int k = kc * 4 + q;
                    float lg = l[k] * scal;
                    lg = (msk[k] == 0.0f) ? -1e9f : lg;
                    float g = -__logf(-__logf(ue[q] + EPSF) + EPSF);
                    float zz = lg + g;   // TAU = 1
                    z[k] = zz;
                    m = fmaxf(m, zz);
                }
            }
            float ssum = 0.0f;
            #pragma unroll
            for (int k = 0; k < K_DIM; k++) {
                float e = __expf(z[k] - m);
                z[k] = e;
                ssum += e;
            }
            float inv = 1.0f / ssum;
            float4* so = (float4*)(s_out + (size_t)n * K_DIM);
            #pragma unroll
            for (int kc = 0; kc < 8; kc++) {
                float s0 = z[kc * 4 + 0] * inv;
                float s1 = z[kc * 4 + 1] * inv;
                float s2 = z[kc * 4 + 2] * inv;
                float s3 = z[kc * 4 + 3] * inv;
                ent_local += s0 * __logf(s0 + EPSF) + s1 * __logf(s1 + EPSF)
                           + s2 * __logf(s2 + EPSF) + s3 * __logf(s3 + EPSF);
                float4 sv = make_float4(s0, s1, s2, s3);
                so[kc] = sv;
                *(float4*)&lsh[t * LSTR + kc * 4] = sv;
            }
        } else {
            #pragma unroll
            for (int j = 0; j < 8; j++)
                *(float4*)&lsh[t * LSTR + j * 4] = make_float4(0.f, 0.f, 0.f, 0.f);
        }
    }
    __syncthreads();

    // ================= pool (s^T @ x) + moments =================
    const int lane = t & 31, grp = t >> 5;
    const int kg3 = lane >> 3;   // k rows kg3*8..+8
    const int cg3 = lane & 7;    // c cols cg3 + 8*j
    int g_lo = bsh[0], g_hi = bsh[127];
    bool single = (g_lo == g_hi);

    for (int g = g_lo; g <= g_hi; g++) {
        // ---- moments: lane = k index, grp = node split ----
        {
            float ss = 0.f, sx = 0.f, sy = 0.f, sq = 0.f;
            bool hit = false;
            #pragma unroll 4
            for (int i = 0; i < 16; i++) {
                int nn = grp * 16 + i;
                if (bsh[nn] != g) continue;
                hit = true;
                float sv = lsh[nn * LSTR + lane];
                float px = psh[nn * 2], py = psh[nn * 2 + 1];
                ss += sv;
                sx += sv * px;
                sy += sv * py;
                sq += sv * (px * px + py * py);
            }
            if (hit) {
                int bk = g * K_DIM + lane;
                atomicAdd(&g_ss[bk], ss);
                atomicAdd(&g_spp[2 * bk + 0], sx);
                atomicAdd(&g_spp[2 * bk + 1], sy);
                atomicAdd(&g_spq[lane], sq);
            }
        }

        // ---- pool accumulation: per-thread 8k x 8c, 16-node split ----
        ull pacc[32];
        #pragma unroll
        for (int i = 0; i < 32; i++) pacc[i] = 0ull;
        #pragma unroll 2
        for (int i = 0; i < 16; i++) {
            int nn = grp * 16 + i;
            if (bsh[nn] != g) continue;
            const float* srow = &lsh[nn * LSTR + kg3 * 8];
            float4 sa = *(const float4*)srow;
            float4 sb = *(const float4*)(srow + 4);
            float s8[8] = {sa.x, sa.y, sa.z, sa.w, sb.x, sb.y, sb.z, sb.w};
            ull xp[4];
            #pragma unroll
            for (int m = 0; m < 4; m++) {
                float x0 = xT[(cg3 + 8 * (2 * m)) * 132 + nn];
                float x1 = xT[(cg3 + 8 * (2 * m + 1)) * 132 + nn];
                xp[m] = pack2(x0, x1);
            }
            #pragma unroll
            for (int kk = 0; kk < 8; kk++) {
                ull s2 = pack2(s8[kk], s8[kk]);
                pacc[kk * 4 + 0] = fma2(s2, xp[0], pacc[kk * 4 + 0]);
                pacc[kk * 4 + 1] = fma2(s2, xp[1], pacc[kk * 4 + 1]);
                pacc[kk * 4 + 2] = fma2(s2, xp[2], pacc[kk * 4 + 2]);
                pacc[kk * 4 + 3] = fma2(s2, xp[3], pacc[kk * 4 + 3]);
            }
        }

        if (single) {
            // tree-reduce 8 node-splits in xT scratch (x no longer needed)
            __syncthreads();
            if (grp >= 4) {
                #pragma unroll
                for (int a = 0; a < 32; a++) {
                    float lo, hi;
                    unpack2(pacc[a], lo, hi);
                    xT[(2 * a + 0) * 132 + (grp - 4) * 32 + lane] = lo;
                    xT[(2 * a + 1) * 132 + (grp - 4) * 32 + lane] = hi;
                }
            }
            __syncthreads();
            if (grp < 4) {
                #pragma unroll
                for (int a = 0; a < 32; a++) {
                    float lo, hi;
                    unpack2(pacc[a], lo, hi);
                    lo += xT[(2 * a + 0) * 132 + grp * 32 + lane];
                    hi += xT[(2 * a + 1) * 132 + grp * 32 + lane];
                    pacc[a] = pack2(lo, hi);
                }
            }
            __syncthreads();
            if (grp == 2 || grp == 3) {
                #pragma unroll
                for (int a = 0; a < 32; a++) {
                    float lo, hi;
                    unpack2(pacc[a], lo, hi);
                    xT[(2 * a + 0) * 132 + (grp - 2) * 32 + lane] = lo;
                    xT[(2 * a + 1) * 132 + (grp - 2) * 32 + lane] = hi;
                }
            }
            __syncthreads();
            if (grp < 2) {
                #pragma unroll
                for (int a = 0; a < 32; a++) {
                    float lo, hi;
                    unpack2(pacc[a], lo, hi);
                    lo += xT[(2 * a + 0) * 132 + grp * 32 + lane];
                    hi += xT[(2 * a + 1) * 132 + grp * 32 + lane];
                    pacc[a] = pack2(lo, hi);
                }
            }
            __syncthreads();
            if (grp == 1) {
                #pragma unroll
                for (int a = 0; a < 32; a++) {
                    float lo, hi;
                    unpack2(pacc[a], lo, hi);
                    xT[(2 * a + 0) * 132 + lane] = lo;
                    xT[(2 * a + 1) * 132 + lane] = hi;
                }
            }
            __syncthreads();
            if (grp == 0) {
                #pragma unroll
                for (int a = 0; a < 32; a++) {
                    int kk = a >> 2, m = a & 3;
                    float lo, hi;
                    unpack2(pacc[a], lo, hi);
                    lo += xT[(2 * a + 0) * 132 + lane];
                    hi += xT[(2 * a + 1) * 132 + lane];
                    int k = kg3 * 8 + kk;
                    atomicAdd(&out[(size_t)g * 2048 + k * 64 + cg3 + 16 * m], lo);
                    atomicAdd(&out[(size_t)g * 2048 + k * 64 + cg3 + 16 * m + 8], hi);
                }
            }
        } else {
            #pragma unroll
            for (int a = 0; a < 32; a++) {
                int kk = a >> 2, m = a & 3;
                float lo, hi;
                unpack2(pacc[a], lo, hi);
                int k = kg3 * 8 + kk;
                if (lo != 0.f) atomicAdd(&out[(size_t)g * 2048 + k * 64 + cg3 + 16 * m], lo);
                if (hi != 0.f) atomicAdd(&out[(size_t)g * 2048 + k * 64 + cg3 + 16 * m + 8], hi);
            }
        }
    }

    // ---- entropy reduction ----
    #pragma unroll
    for (int o = 16; o; o >>= 1) ent_local += __shfl_xor_sync(0xffffffffu, ent_local, o);
    if (lane == 0) wsum[grp] = ent_local;
    __syncthreads();
    if (t == 0) {
        float w = 0.f;
        #pragma unroll
        for (int i = 0; i < 8; i++) w += wsum[i];
        atomicAdd(&g_ent, w);
    }
}

// ---------------- kernel C: finalize ----------------
__global__ __launch_bounds__(512)
void hp_final_kernel(const float* __restrict__ amask, float* __restrict__ out, int N) {
    __shared__ float mush[B_DIM * K_DIM][2];
    __shared__ float red[16];

    const size_t off_scalars = (size_t)OFF_S + (size_t)N * K_DIM;
    const size_t OFF_ENT  = off_scalars + 0;
    const size_t OFF_DIV  = off_scalars + 1;
    const size_t OFF_SPAT = off_scalars + 2;
    const size_t OFF_PRUN = off_scalars + 3;
    const size_t OFF_SPAR = off_scalars + 4;
    const size_t OFF_SEP  = off_scalars + 5;
    const size_t OFF_MU   = off_scalars + 6;

    int t = threadIdx.x;
    int bk = t;
    float ssv = g_ss[bk];
    float denom = ssv + EPSF;
    float mux = g_spp[2 * bk] / denom;
    float muy = g_spp[2 * bk + 1] / denom;
    mush[bk][0] = mux;
    mush[bk][1] = muy;
    out[OFF_MU + 2 * bk] = mux;
    out[OFF_MU + 2 * bk + 1] = muy;
    __syncthreads();

    int b = bk >> 5, k1 = bk & 31;
    float sep = 0.0f;
    #pragma unroll
    for (int k2 = 0; k2 < K_DIM; k2++) {
        if (k2 == k1) continue;
        float dx = mux - mush[b * K_DIM + k2][0];
        float dy = muy - mush[b * K_DIM + k2][1];
        sep += 1.0f / (dx * dx + dy * dy + 1.0f);
    }
    #pragma unroll
    for (int o = 16; o; o >>= 1) sep += __shfl_xor_sync(0xffffffffu, sep, o);
    if ((t & 31) == 0) red[t >> 5] = sep;
    __syncthreads();

    if (t == 0) {
        float tot = 0.0f;
        for (int i = 0; i < 16; i++) tot += red[i];
        out[OFF_SEP] = tot / ((float)(K_DIM * (K_DIM - 1)) + EPSF);

        float div = 0.0f, spat = 0.0f, prun = 0.0f, spars = 0.0f;
        for (int k = 0; k < K_DIM; k++) {
            float ss = 0.0f, sx = 0.0f, sy = 0.0f;
            for (int bb = 0; bb < B_DIM; bb++) {
                int idx = bb * K_DIM + k;
                ss += g_ss[idx];
                sx += g_spp[2 * idx];
                sy += g_spp[2 * idx + 1];
            }
            float avg = ss / (float)N;
            div += avg * __logf(avg + EPSF);
            float sse = ss + EPSF;
            float mgx = sx / sse, mgy = sy / sse;
            float var = g_spq[k] / sse
                        - 2.0f * (mgx * (sx / sse) + mgy * (sy / sse))
                        + (mgx * mgx + mgy * mgy);
            spat += var;
            float mk = amask[k];
            prun += fabsf(avg * (1.0f - mk));
            spars += mk;
        }
        out[OFF_ENT]  = -g_ent / (float)N;
        out[OFF_DIV]  = div;
        out[OFF_SPAT] = spat / (float)K_DIM;
        out[OFF_PRUN] = prun / (float)K_DIM;
        out[OFF_SPAR] = spars / (float)K_DIM;
    }
}

// ---------------- launcher ----------------
extern "C" void kernel_launch(void* const* d_in, const int* in_sizes, int n_in,
                              void* d_out, int out_size) {
    (void)n_in; (void)out_size;
    const float* x       = (const float*)d_in[0];
    const int*   batch   = (const int*)d_in[1];
    const float* pos     = (const float*)d_in[2];
    const float* u       = (const float*)d_in[3];
    const float* W1      = (const float*)d_in[4];
    const float* b1      = (const float*)d_in[5];
    const float* W2      = (const float*)d_in[6];
    const float* b2      = (const float*)d_in[7];
    const float* scaling = (const float*)d_in[8];
    const float* amask   = (const float*)d_in[9];
    float* out = (float*)d_out;

    int N = in_sizes[0] / C_DIM;
    int gtiles = (N + 127) / 128;

    cudaFuncSetAttribute(hp_fused, cudaFuncAttributeMaxDynamicSharedMemorySize,
                         SMEM_BYTES);

    hp_zero_kernel<<<64, 256>>>(out);
    hp_fused<<<gtiles, 256, SMEM_BYTES>>>(x, batch, pos, u, W1, b1, W2, b2,
                                          scaling, amask, out, out + OFF_S, N);
    hp_final_kernel<<<1, 512>>>(amask, out, N);
}